// round 1
// baseline (speedup 1.0000x reference)
#include <cuda_runtime.h>
#include <math.h>

#define B_  2
#define C_  32
#define D_  24
#define H_  64
#define W_  128
#define S_  (D_*H_*W_)           /* 196608 positions per batch */
#define NTOT ((size_t)C_*(size_t)S_)  /* 6291456 elems per batch */
#define HEADS_ 2
#define DQK_ 16
#define DV_  16
#define FC_  256
#define NS_  256

/* ---------------- persistent scratch (no allocations allowed) -------------- */
__device__ double g_s1[B_], g_q1[B_];   /* sum / sumsq of cost, per batch */
__device__ double g_s2[B_], g_q2[B_];   /* sum / sumsq of y = cost + g*out */
__device__ float  g_K [B_][HEADS_][NS_][DQK_];  /* pre-scaled by DQK^-0.5 */
__device__ float  g_V [B_][HEADS_][NS_][DV_];
__device__ float  g_Wq[B_][C_][C_];     /* GN-folded Q projection */
__device__ float  g_qb[B_][C_];         /* GN-folded Q bias */

/* ---------------- K0: zero accumulators ----------------------------------- */
__global__ void k_zero() {
    int i = threadIdx.x;
    if (i < B_) { g_s1[i] = 0.0; g_q1[i] = 0.0; g_s2[i] = 0.0; g_q2[i] = 0.0; }
}

/* ---------------- K1: per-batch sum / sumsq of cost ------------------------ */
__global__ void k_reduce_in(const float* __restrict__ cost) {
    int b = blockIdx.y;
    const float4* p = (const float4*)(cost + (size_t)b * NTOT);
    const int n4 = (int)(NTOT / 4);
    float s = 0.f, q = 0.f;
    for (int i = blockIdx.x * blockDim.x + threadIdx.x; i < n4;
         i += gridDim.x * blockDim.x) {
        float4 v = p[i];
        s += v.x + v.y + v.z + v.w;
        q += v.x*v.x + v.y*v.y + v.z*v.z + v.w*v.w;
    }
    #pragma unroll
    for (int o = 16; o; o >>= 1) {
        s += __shfl_down_sync(0xffffffffu, s, o);
        q += __shfl_down_sync(0xffffffffu, q, o);
    }
    __shared__ float ss[8], sq[8];
    int lane = threadIdx.x & 31, w = threadIdx.x >> 5;
    if (lane == 0) { ss[w] = s; sq[w] = q; }
    __syncthreads();
    if (threadIdx.x == 0) {
        float ts = 0.f, tq = 0.f;
        #pragma unroll
        for (int i = 0; i < 8; i++) { ts += ss[i]; tq += sq[i]; }
        atomicAdd(&g_s1[b], (double)ts);
        atomicAdd(&g_q1[b], (double)tq);
    }
}

/* ---------------- K2a: K/V projections from feat_s4 ------------------------ */
/* grid (NS_, B_), block 64: thread t<32 -> K output row t; t>=32 -> V row t-32 */
__global__ void k_kv(const float* __restrict__ feat,
                     const float* __restrict__ Wk,
                     const float* __restrict__ Wv) {
    int n = blockIdx.x, b = blockIdx.y, t = threadIdx.x;
    __shared__ float sf[FC_];
    for (int i = t; i < FC_; i += 64)
        sf[i] = feat[((size_t)b * FC_ + i) * NS_ + n];
    __syncthreads();
    const float* Wr = (t < 32) ? (Wk + (size_t)t * FC_)
                               : (Wv + (size_t)(t - 32) * FC_);
    const float4* W4 = (const float4*)Wr;
    const float4* f4 = (const float4*)sf;
    float acc = 0.f;
    #pragma unroll 8
    for (int i = 0; i < FC_ / 4; i++) {
        float4 w = W4[i]; float4 f = f4[i];
        acc += w.x*f.x + w.y*f.y + w.z*f.z + w.w*f.w;
    }
    if (t < 32) g_K[b][t >> 4][n][t & 15] = acc * 0.25f;  /* DQK^-0.5 = 1/4 */
    else { int u = t - 32; g_V[b][u >> 4][n][u & 15] = acc; }
}

/* ---------------- K2b: GN-folded Q projection ------------------------------ */
/* grid (B_), block 1024: t -> (o = t>>5, c = t&31) */
__global__ void k_wq(const float* __restrict__ Wq,
                     const float* __restrict__ gw,
                     const float* __restrict__ gb) {
    int b = blockIdx.x, t = threadIdx.x;
    double mean = g_s1[b] / (double)NTOT;
    double var  = g_q1[b] / (double)NTOT - mean * mean;
    float inv = (float)(1.0 / sqrt(var + 1e-5));
    float mu  = (float)mean;
    int o = t >> 5, c = t & 31;
    g_Wq[b][o][c] = Wq[o * C_ + c] * gw[c] * inv;
    if (t < C_) {
        float acc = 0.f;
        for (int cc = 0; cc < C_; cc++)
            acc += Wq[t * C_ + cc] * (gb[cc] - gw[cc] * mu * inv);
        g_qb[b][t] = acc;
    }
}

/* ---------------- K3: fused attention mainloop ----------------------------- */
/* grid (S_/256, B_), 256 threads, 1 thread = 1 spatial position.
   smem: K[2][256][16], V[2][256][16], Wq_eff[32][32], Wo[32][32], qb[32]     */
__global__ void __launch_bounds__(256, 2)
k_attn(const float* __restrict__ cost, const float* __restrict__ Wo,
       const float* __restrict__ gammap, float* __restrict__ y) {
    extern __shared__ float sm[];
    float* sK  = sm;            /* 8192 */
    float* sV  = sm + 8192;     /* 8192 */
    float* sWq = sm + 16384;    /* 1024 */
    float* sWo = sm + 17408;    /* 1024 */
    float* sqb = sm + 18432;    /* 32   */

    int b = blockIdx.y;
    int tid = threadIdx.x;

    {   /* cooperative smem fill */
        const float4* gK4  = (const float4*)&g_K[b][0][0][0];
        const float4* gV4  = (const float4*)&g_V[b][0][0][0];
        const float4* gWq4 = (const float4*)&g_Wq[b][0][0];
        const float4* gWo4 = (const float4*)Wo;
        float4* sK4  = (float4*)sK;
        float4* sV4  = (float4*)sV;
        #pragma unroll
        for (int r = 0; r < 8; r++) {
            sK4[tid + 256 * r] = gK4[tid + 256 * r];
            sV4[tid + 256 * r] = gV4[tid + 256 * r];
        }
        ((float4*)sWq)[tid & 255] = gWq4[tid & 255];   /* 256 float4 */
        ((float4*)sWo)[tid & 255] = gWo4[tid & 255];
        if (tid < 32) sqb[tid] = g_qb[b][tid];
    }
    __syncthreads();

    int s = blockIdx.x * 256 + tid;
    const float* xp = cost + (size_t)b * NTOT + s;

    /* Phase A: q = Wq_eff * x + qb (GN folded in) */
    float q[32];
    {
        float x[32];
        #pragma unroll
        for (int c = 0; c < 32; c++) x[c] = xp[(size_t)c * S_];
        #pragma unroll
        for (int o = 0; o < 32; o++) {
            float acc = sqb[o];
            const float4* wr = (const float4*)(sWq + o * 32);
            #pragma unroll
            for (int c4 = 0; c4 < 8; c4++) {
                float4 w = wr[c4];
                acc += w.x*x[c4*4+0] + w.y*x[c4*4+1]
                     + w.z*x[c4*4+2] + w.w*x[c4*4+3];
            }
            q[o] = acc;
        }
    }

    /* Phase B: per-head softmax-attention over 256 tokens (online, no max) */
    float z[32];
    #pragma unroll
    for (int h = 0; h < HEADS_; h++) {
        const float4* Kp = (const float4*)(sK + h * NS_ * 16);
        const float4* Vp = (const float4*)(sV + h * NS_ * 16);
        const float* qh = q + h * 16;
        float acc[16];
        #pragma unroll
        for (int d = 0; d < 16; d++) acc[d] = 0.f;
        float ssum = 0.f;
        #pragma unroll 4
        for (int n = 0; n < NS_; n++) {
            float4 k0 = Kp[n*4+0], k1 = Kp[n*4+1], k2 = Kp[n*4+2], k3 = Kp[n*4+3];
            float l = qh[0]*k0.x + qh[1]*k0.y + qh[2]*k0.z + qh[3]*k0.w
                    + qh[4]*k1.x + qh[5]*k1.y + qh[6]*k1.z + qh[7]*k1.w
                    + qh[8]*k2.x + qh[9]*k2.y + qh[10]*k2.z + qh[11]*k2.w
                    + qh[12]*k3.x + qh[13]*k3.y + qh[14]*k3.z + qh[15]*k3.w;
            float e = __expf(l);
            ssum += e;
            float4 v0 = Vp[n*4+0], v1 = Vp[n*4+1], v2 = Vp[n*4+2], v3 = Vp[n*4+3];
            acc[0]  += e*v0.x; acc[1]  += e*v0.y; acc[2]  += e*v0.z; acc[3]  += e*v0.w;
            acc[4]  += e*v1.x; acc[5]  += e*v1.y; acc[6]  += e*v1.z; acc[7]  += e*v1.w;
            acc[8]  += e*v2.x; acc[9]  += e*v2.y; acc[10] += e*v2.z; acc[11] += e*v2.w;
            acc[12] += e*v3.x; acc[13] += e*v3.y; acc[14] += e*v3.z; acc[15] += e*v3.w;
        }
        float r = 1.f / ssum;
        #pragma unroll
        for (int d = 0; d < 16; d++) z[h * 16 + d] = acc[d] * r;
    }

    /* Phase C: Wo projection + residual; write y; accumulate output-GN stats */
    float g = __ldg(gammap);
    float lsum = 0.f, lsq = 0.f;
    float* yp = y + (size_t)b * NTOT + s;
    #pragma unroll
    for (int c = 0; c < 32; c++) {
        const float4* wr = (const float4*)(sWo + c * 32);
        float o = 0.f;
        #pragma unroll
        for (int j4 = 0; j4 < 8; j4++) {
            float4 w = wr[j4];
            o += w.x*z[j4*4+0] + w.y*z[j4*4+1] + w.z*z[j4*4+2] + w.w*z[j4*4+3];
        }
        float yv = xp[(size_t)c * S_] + g * o;
        yp[(size_t)c * S_] = yv;
        lsum += yv; lsq += yv * yv;
    }
    #pragma unroll
    for (int off = 16; off; off >>= 1) {
        lsum += __shfl_down_sync(0xffffffffu, lsum, off);
        lsq  += __shfl_down_sync(0xffffffffu, lsq,  off);
    }
    __shared__ float rs[8], rq[8];
    int lane = tid & 31, w = tid >> 5;
    if (lane == 0) { rs[w] = lsum; rq[w] = lsq; }
    __syncthreads();
    if (tid == 0) {
        float ts = 0.f, tq = 0.f;
        #pragma unroll
        for (int i = 0; i < 8; i++) { ts += rs[i]; tq += rq[i]; }
        atomicAdd(&g_s2[b], (double)ts);
        atomicAdd(&g_q2[b], (double)tq);
    }
}

/* ---------------- K4: in-place output GroupNorm ---------------------------- */
/* grid (48, B_*C_), block 256 */
__global__ void k_final(float* __restrict__ out,
                        const float* __restrict__ gw,
                        const float* __restrict__ gb) {
    int bc = blockIdx.y;
    int b = bc >> 5, c = bc & 31;
    double mean = g_s2[b] / (double)NTOT;
    double var  = g_q2[b] / (double)NTOT - mean * mean;
    float inv = (float)(1.0 / sqrt(var + 1e-5));
    float a  = gw[c] * inv;
    float bb = gb[c] - gw[c] * (float)mean * inv;
    float4* p = (float4*)(out + ((size_t)b * C_ + c) * S_);
    const int n4 = S_ / 4;
    for (int i = blockIdx.x * blockDim.x + threadIdx.x; i < n4;
         i += gridDim.x * blockDim.x) {
        float4 v = p[i];
        v.x = a*v.x + bb; v.y = a*v.y + bb; v.z = a*v.z + bb; v.w = a*v.w + bb;
        p[i] = v;
    }
}

/* ---------------- launch --------------------------------------------------- */
extern "C" void kernel_launch(void* const* d_in, const int* in_sizes, int n_in,
                              void* d_out, int out_size) {
    const float* cost  = (const float*)d_in[0];
    const float* feat  = (const float*)d_in[1];
    const float* Wq    = (const float*)d_in[2];
    const float* Wk    = (const float*)d_in[3];
    const float* Wv    = (const float*)d_in[4];
    const float* Wo    = (const float*)d_in[5];
    const float* gniw  = (const float*)d_in[6];
    const float* gnib  = (const float*)d_in[7];
    const float* gnow  = (const float*)d_in[8];
    const float* gnob  = (const float*)d_in[9];
    const float* gamma = (const float*)d_in[10];
    float* out = (float*)d_out;

    const int smem3 = 18464 * (int)sizeof(float);  /* 73856 B dynamic */
    cudaFuncSetAttribute(k_attn, cudaFuncAttributeMaxDynamicSharedMemorySize, smem3);

    k_zero<<<1, 32>>>();
    k_reduce_in<<<dim3(192, B_), 256>>>(cost);
    k_kv<<<dim3(NS_, B_), 64>>>(feat, Wk, Wv);
    k_wq<<<B_, 1024>>>(Wq, gniw, gnib);
    k_attn<<<dim3(S_ / 256, B_), 256, smem3>>>(cost, Wo, gamma, out);
    k_final<<<dim3(48, B_ * C_), 256>>>(out, gnow, gnob);
}

// round 4
// speedup vs baseline: 3.9543x; 3.9543x over previous
#include <cuda_runtime.h>
#include <cuda_bf16.h>
#include <math.h>

#define B_  2
#define C_  32
#define S_  (24*64*128)               /* 196608 positions per batch */
#define NTOT ((size_t)C_*(size_t)S_)  /* 6291456 elems per batch */
#define NS_  256
#define FC_  256

/* ===================== persistent device scratch ========================== */
__device__ double g_s1[B_], g_q1[B_];
__device__ double g_s2[B_], g_q2[B_];
__device__ float  g_qb[B_][C_];
__device__ __align__(16) __nv_bfloat16 g_Kb[B_][2][256][16];  /* [b][h][token][dqk], pre-scaled */
__device__ __align__(16) __nv_bfloat16 g_Vt[B_][2][16][256];  /* [b][h][dv][token] */
__device__ __align__(16) __nv_bfloat16 g_Wqb[B_][32][32];     /* GN-folded */
__device__ __align__(16) __nv_bfloat16 g_Wob[32][32];

/* ===================== helpers ============================================ */
__device__ __forceinline__ float fexp(float x) {   /* Schraudolph, ~2% max rel err */
    return __int_as_float(__float2int_rn(fmaf(x, 12102203.0f, 1064866805.0f)));
}
__device__ __forceinline__ unsigned packbf(float lo, float hi) {
    __nv_bfloat162 h2 = __floats2bfloat162_rn(lo, hi);
    return *(unsigned*)&h2;
}
/* D += A(16x16 bf16,row) * B(16x8 bf16,col) ; f32 accum */
__device__ __forceinline__ void mma16816(float* d, const unsigned* a, const unsigned* b) {
    asm volatile("mma.sync.aligned.m16n8k16.row.col.f32.bf16.bf16.f32 "
        "{%0,%1,%2,%3}, {%4,%5,%6,%7}, {%8,%9}, {%0,%1,%2,%3};"
        : "+f"(d[0]), "+f"(d[1]), "+f"(d[2]), "+f"(d[3])
        : "r"(a[0]), "r"(a[1]), "r"(a[2]), "r"(a[3]), "r"(b[0]), "r"(b[1]));
}

/* ===================== K0: zero accumulators ============================== */
__global__ void k_zero() {
    int i = threadIdx.x;
    if (i < B_) { g_s1[i] = 0.0; g_q1[i] = 0.0; g_s2[i] = 0.0; g_q2[i] = 0.0; }
}

/* ===================== K1: per-batch stats of cost ======================== */
__global__ void k_reduce_in(const float* __restrict__ cost) {
    int b = blockIdx.y;
    const float4* p = (const float4*)(cost + (size_t)b * NTOT);
    const int n4 = (int)(NTOT / 4);
    float s = 0.f, q = 0.f;
    for (int i = blockIdx.x * blockDim.x + threadIdx.x; i < n4; i += gridDim.x * blockDim.x) {
        float4 v = p[i];
        s += v.x + v.y + v.z + v.w;
        q += v.x*v.x + v.y*v.y + v.z*v.z + v.w*v.w;
    }
    #pragma unroll
    for (int o = 16; o; o >>= 1) {
        s += __shfl_down_sync(0xffffffffu, s, o);
        q += __shfl_down_sync(0xffffffffu, q, o);
    }
    __shared__ float ss[8], sq[8];
    int lane = threadIdx.x & 31, w = threadIdx.x >> 5;
    if (lane == 0) { ss[w] = s; sq[w] = q; }
    __syncthreads();
    if (threadIdx.x == 0) {
        float ts = 0.f, tq = 0.f;
        #pragma unroll
        for (int i = 0; i < 8; i++) { ts += ss[i]; tq += sq[i]; }
        atomicAdd(&g_s1[b], (double)ts);
        atomicAdd(&g_q1[b], (double)tq);
    }
}

/* ===================== K2a: K/V projections =============================== */
__global__ void k_kv(const float* __restrict__ feat,
                     const float* __restrict__ Wk,
                     const float* __restrict__ Wv) {
    int n = blockIdx.x, b = blockIdx.y, t = threadIdx.x;
    __shared__ float sf[FC_];
    for (int i = t; i < FC_; i += 64)
        sf[i] = feat[((size_t)b * FC_ + i) * NS_ + n];
    __syncthreads();
    const float* Wr = (t < 32) ? (Wk + (size_t)t * FC_) : (Wv + (size_t)(t - 32) * FC_);
    const float4* W4 = (const float4*)Wr;
    const float4* f4 = (const float4*)sf;
    float acc = 0.f;
    #pragma unroll 8
    for (int i = 0; i < FC_ / 4; i++) {
        float4 w = W4[i]; float4 f = f4[i];
        acc += w.x*f.x + w.y*f.y + w.z*f.z + w.w*f.w;
    }
    if (t < 32) g_Kb[b][t >> 4][n][t & 15] = __float2bfloat16(acc * 0.25f);
    else { int u = t - 32; g_Vt[b][u >> 4][u & 15][n] = __float2bfloat16(acc); }
}

/* ===================== K2b: GN-folded Wq + Wo + bias ====================== */
__global__ void k_wq(const float* __restrict__ Wq, const float* __restrict__ Wo,
                     const float* __restrict__ gw, const float* __restrict__ gb) {
    int b = blockIdx.x, t = threadIdx.x;
    double mean = g_s1[b] / (double)NTOT;
    double var  = g_q1[b] / (double)NTOT - mean * mean;
    float inv = (float)(1.0 / sqrt(var + 1e-5));
    float mu  = (float)mean;
    int o = t >> 5, c = t & 31;
    g_Wqb[b][o][c] = __float2bfloat16(Wq[o * C_ + c] * gw[c] * inv);
    if (b == 0) g_Wob[o][c] = __float2bfloat16(Wo[o * C_ + c]);
    if (t < C_) {
        float acc = 0.f;
        for (int cc = 0; cc < C_; cc++)
            acc += Wq[t * C_ + cc] * (gb[cc] - gw[cc] * mu * inv);
        g_qb[b][t] = acc;
    }
}

/* ===================== K3: mma.sync flash attention ======================= */
/* grid (1536, B_), 128 threads; 1 CTA = 128 positions, each warp owns 32 rows.
   smem (static, padded rows for conflict-free fragment loads):
     sK : [2][256] rows of 48B (16 bf16 data + pad)
     sV : [2][16]  rows of 528B (256 bf16 + pad)
     sWq/sWo : [32] rows of 80B (32 bf16 + pad)                              */
#define SM_K   0
#define SM_V   24576
#define SM_WQ  41472
#define SM_WO  44032
#define SM_QB  46592
#define SM_RED 46720
#define SM_BYTES 46784

__global__ void __launch_bounds__(128, 4)
k_attn_mma(const float* __restrict__ cost, const float* __restrict__ gammap,
           float* __restrict__ y) {
    __shared__ __align__(16) unsigned char sm[SM_BYTES];
    const int tid = threadIdx.x;
    const int w = tid >> 5, lane = tid & 31;
    const int gid = lane >> 2, tig = lane & 3;
    const int b = blockIdx.y;

    {   /* cooperative smem fill from staged global tiles */
        const uint4* srcK = (const uint4*)&g_Kb[b][0][0][0];   /* 512 rows x 32B */
        for (int i = tid; i < 1024; i += 128)
            *(uint4*)(sm + SM_K + (i >> 1) * 48 + (i & 1) * 16) = srcK[i];
        const uint4* srcV = (const uint4*)&g_Vt[b][0][0][0];   /* 32 rows x 512B */
        for (int i = tid; i < 1024; i += 128)
            *(uint4*)(sm + SM_V + (i >> 5) * 528 + (i & 31) * 16) = srcV[i];
        const uint4* srcQ = (const uint4*)&g_Wqb[b][0][0];     /* 32 rows x 64B */
        for (int i = tid; i < 128; i += 128)
            *(uint4*)(sm + SM_WQ + (i >> 2) * 80 + (i & 3) * 16) = srcQ[i];
        const uint4* srcO = (const uint4*)&g_Wob[0][0];
        for (int i = tid; i < 128; i += 128)
            *(uint4*)(sm + SM_WO + (i >> 2) * 80 + (i & 3) * 16) = srcO[i];
        if (tid < 32) ((float*)(sm + SM_QB))[tid] = g_qb[b][tid];
    }
    __syncthreads();

    const int pos0 = blockIdx.x * 128;
    const int rabs[2] = { pos0 + w * 32 + gid, pos0 + w * 32 + 16 + gid };
    const float* xb = cost + (size_t)b * NTOT;
    const float* sqbf = (const float*)(sm + SM_QB);

    /* ---- Phase A: Qproj  Q = X @ Wq_eff^T + qb ---- */
    unsigned qf[2][2][4];   /* [head][mtile][4] A-fragments of Q (bf16) */
    {
        unsigned xa[2][2][4];   /* [mtile][ktile] A-frags of X */
        #pragma unroll
        for (int mt = 0; mt < 2; mt++) {
            int r0 = rabs[mt], r1 = r0 + 8;
            #pragma unroll
            for (int kt = 0; kt < 2; kt++) {
                int c = kt * 16 + tig * 2;
                xa[mt][kt][0] = packbf(xb[(size_t)c*S_ + r0],     xb[(size_t)(c+1)*S_ + r0]);
                xa[mt][kt][1] = packbf(xb[(size_t)c*S_ + r1],     xb[(size_t)(c+1)*S_ + r1]);
                xa[mt][kt][2] = packbf(xb[(size_t)(c+8)*S_ + r0], xb[(size_t)(c+9)*S_ + r0]);
                xa[mt][kt][3] = packbf(xb[(size_t)(c+8)*S_ + r1], xb[(size_t)(c+9)*S_ + r1]);
            }
        }
        float qc[2][4][4];
        #pragma unroll
        for (int mt = 0; mt < 2; mt++)
            #pragma unroll
            for (int nt = 0; nt < 4; nt++)
                #pragma unroll
                for (int j = 0; j < 4; j++) qc[mt][nt][j] = 0.f;
        #pragma unroll
        for (int nt = 0; nt < 4; nt++) {
            const unsigned char* Wr = sm + SM_WQ + (nt * 8 + gid) * 80;
            unsigned bq[2][2];
            bq[0][0] = *(const unsigned*)(Wr + tig * 4);
            bq[0][1] = *(const unsigned*)(Wr + 16 + tig * 4);
            bq[1][0] = *(const unsigned*)(Wr + 32 + tig * 4);
            bq[1][1] = *(const unsigned*)(Wr + 48 + tig * 4);
            #pragma unroll
            for (int mt = 0; mt < 2; mt++) {
                mma16816(qc[mt][nt], xa[mt][0], bq[0]);
                mma16816(qc[mt][nt], xa[mt][1], bq[1]);
            }
            float b0 = sqbf[nt * 8 + tig * 2], b1 = sqbf[nt * 8 + tig * 2 + 1];
            #pragma unroll
            for (int mt = 0; mt < 2; mt++) {
                qc[mt][nt][0] += b0; qc[mt][nt][1] += b1;
                qc[mt][nt][2] += b0; qc[mt][nt][3] += b1;
            }
        }
        #pragma unroll
        for (int h = 0; h < 2; h++)
            #pragma unroll
            for (int mt = 0; mt < 2; mt++) {
                qf[h][mt][0] = packbf(qc[mt][2*h][0],   qc[mt][2*h][1]);
                qf[h][mt][1] = packbf(qc[mt][2*h][2],   qc[mt][2*h][3]);
                qf[h][mt][2] = packbf(qc[mt][2*h+1][0], qc[mt][2*h+1][1]);
                qf[h][mt][3] = packbf(qc[mt][2*h+1][2], qc[mt][2*h+1][3]);
            }
    }

    /* ---- Phase B: per-head streaming softmax-attention ---- */
    unsigned zf[2][2][4];   /* [mtile][ktile=head] Z A-fragments */
    #pragma unroll
    for (int h = 0; h < 2; h++) {
        const unsigned char* Kh = sm + SM_K + h * 12288;
        const unsigned char* Vh = sm + SM_V + h * 8448;
        float oa[2][2][4];
        #pragma unroll
        for (int mt = 0; mt < 2; mt++)
            #pragma unroll
            for (int dt = 0; dt < 2; dt++)
                #pragma unroll
                for (int j = 0; j < 4; j++) oa[mt][dt][j] = 0.f;
        float s0[2] = {0.f, 0.f}, s1[2] = {0.f, 0.f};
        #pragma unroll 4
        for (int nt2 = 0; nt2 < 16; nt2++) {
            const int t0 = nt2 * 16;
            unsigned kb[2][2], vb[2][2];
            kb[0][0] = *(const unsigned*)(Kh + (t0 + gid) * 48 + tig * 4);
            kb[0][1] = *(const unsigned*)(Kh + (t0 + gid) * 48 + 16 + tig * 4);
            kb[1][0] = *(const unsigned*)(Kh + (t0 + 8 + gid) * 48 + tig * 4);
            kb[1][1] = *(const unsigned*)(Kh + (t0 + 8 + gid) * 48 + 16 + tig * 4);
            vb[0][0] = *(const unsigned*)(Vh + gid * 528 + t0 * 2 + tig * 4);
            vb[0][1] = *(const unsigned*)(Vh + gid * 528 + t0 * 2 + 16 + tig * 4);
            vb[1][0] = *(const unsigned*)(Vh + (8 + gid) * 528 + t0 * 2 + tig * 4);
            vb[1][1] = *(const unsigned*)(Vh + (8 + gid) * 528 + t0 * 2 + 16 + tig * 4);
            #pragma unroll
            for (int mt = 0; mt < 2; mt++) {
                float sc0[4] = {0.f,0.f,0.f,0.f}, sc1[4] = {0.f,0.f,0.f,0.f};
                mma16816(sc0, qf[h][mt], kb[0]);
                mma16816(sc1, qf[h][mt], kb[1]);
                float e0 = fexp(sc0[0]), e1 = fexp(sc0[1]);
                float e2 = fexp(sc0[2]), e3 = fexp(sc0[3]);
                float f0 = fexp(sc1[0]), f1 = fexp(sc1[1]);
                float f2 = fexp(sc1[2]), f3 = fexp(sc1[3]);
                s0[mt] += (e0 + e1) + (f0 + f1);
                s1[mt] += (e2 + e3) + (f2 + f3);
                unsigned pa[4] = { packbf(e0, e1), packbf(e2, e3),
                                   packbf(f0, f1), packbf(f2, f3) };
                mma16816(oa[mt][0], pa, vb[0]);
                mma16816(oa[mt][1], pa, vb[1]);
            }
        }
        #pragma unroll
        for (int mt = 0; mt < 2; mt++) {
            float a0 = s0[mt], a1 = s1[mt];
            a0 += __shfl_xor_sync(0xffffffffu, a0, 1);
            a0 += __shfl_xor_sync(0xffffffffu, a0, 2);
            a1 += __shfl_xor_sync(0xffffffffu, a1, 1);
            a1 += __shfl_xor_sync(0xffffffffu, a1, 2);
            float i0 = 1.f / a0, i1 = 1.f / a1;
            zf[mt][h][0] = packbf(oa[mt][0][0] * i0, oa[mt][0][1] * i0);
            zf[mt][h][1] = packbf(oa[mt][0][2] * i1, oa[mt][0][3] * i1);
            zf[mt][h][2] = packbf(oa[mt][1][0] * i0, oa[mt][1][1] * i0);
            zf[mt][h][3] = packbf(oa[mt][1][2] * i1, oa[mt][1][3] * i1);
        }
    }

    /* ---- Phase C: Y = Z @ Wo^T ; residual, write, output-GN stats ---- */
    float gam = __ldg(gammap);
    float lsum = 0.f, lsq = 0.f;
    float* yb = y + (size_t)b * NTOT;
    #pragma unroll
    for (int nt = 0; nt < 4; nt++) {
        const unsigned char* Wr = sm + SM_WO + (nt * 8 + gid) * 80;
        unsigned bo[2][2];
        bo[0][0] = *(const unsigned*)(Wr + tig * 4);
        bo[0][1] = *(const unsigned*)(Wr + 16 + tig * 4);
        bo[1][0] = *(const unsigned*)(Wr + 32 + tig * 4);
        bo[1][1] = *(const unsigned*)(Wr + 48 + tig * 4);
        #pragma unroll
        for (int mt = 0; mt < 2; mt++) {
            float yc[4] = {0.f, 0.f, 0.f, 0.f};
            mma16816(yc, zf[mt][0], bo[0]);
            mma16816(yc, zf[mt][1], bo[1]);
            int ch = nt * 8 + tig * 2;
            int r0 = rabs[mt];
            size_t i00 = (size_t)ch * S_ + r0;
            size_t i01 = i00 + S_;
            float y00 = xb[i00]     + gam * yc[0];
            float y01 = xb[i01]     + gam * yc[1];
            float y10 = xb[i00 + 8] + gam * yc[2];
            float y11 = xb[i01 + 8] + gam * yc[3];
            yb[i00] = y00; yb[i01] = y01; yb[i00 + 8] = y10; yb[i01 + 8] = y11;
            lsum += (y00 + y01) + (y10 + y11);
            lsq  += (y00*y00 + y01*y01) + (y10*y10 + y11*y11);
        }
    }
    #pragma unroll
    for (int o = 16; o; o >>= 1) {
        lsum += __shfl_down_sync(0xffffffffu, lsum, o);
        lsq  += __shfl_down_sync(0xffffffffu, lsq,  o);
    }
    float* red = (float*)(sm + SM_RED);
    if (lane == 0) { red[w] = lsum; red[4 + w] = lsq; }
    __syncthreads();
    if (tid == 0) {
        float ts = red[0] + red[1] + red[2] + red[3];
        float tq = red[4] + red[5] + red[6] + red[7];
        atomicAdd(&g_s2[b], (double)ts);
        atomicAdd(&g_q2[b], (double)tq);
    }
}

/* ===================== K4: in-place output GroupNorm ====================== */
__global__ void k_final(float* __restrict__ out,
                        const float* __restrict__ gw, const float* __restrict__ gb) {
    int bc = blockIdx.y;
    int b = bc >> 5, c = bc & 31;
    double mean = g_s2[b] / (double)NTOT;
    double var  = g_q2[b] / (double)NTOT - mean * mean;
    float inv = (float)(1.0 / sqrt(var + 1e-5));
    float a  = gw[c] * inv;
    float bb = gb[c] - gw[c] * (float)mean * inv;
    float4* p = (float4*)(out + ((size_t)b * C_ + c) * S_);
    const int n4 = S_ / 4;
    for (int i = blockIdx.x * blockDim.x + threadIdx.x; i < n4; i += gridDim.x * blockDim.x) {
        float4 v = p[i];
        v.x = a*v.x + bb; v.y = a*v.y + bb; v.z = a*v.z + bb; v.w = a*v.w + bb;
        p[i] = v;
    }
}

/* ===================== launch ============================================= */
extern "C" void kernel_launch(void* const* d_in, const int* in_sizes, int n_in,
                              void* d_out, int out_size) {
    const float* cost  = (const float*)d_in[0];
    const float* feat  = (const float*)d_in[1];
    const float* Wq    = (const float*)d_in[2];
    const float* Wk    = (const float*)d_in[3];
    const float* Wv    = (const float*)d_in[4];
    const float* Wo    = (const float*)d_in[5];
    const float* gniw  = (const float*)d_in[6];
    const float* gnib  = (const float*)d_in[7];
    const float* gnow  = (const float*)d_in[8];
    const float* gnob  = (const float*)d_in[9];
    const float* gamma = (const float*)d_in[10];
    float* out = (float*)d_out;

    k_zero<<<1, 32>>>();
    k_reduce_in<<<dim3(192, B_), 256>>>(cost);
    k_kv<<<dim3(NS_, B_), 64>>>(feat, Wk, Wv);
    k_wq<<<B_, 1024>>>(Wq, Wo, gniw, gnib);
    k_attn_mma<<<dim3(S_ / 128, B_), 128>>>(cost, gamma, out);
    k_final<<<dim3(48, B_ * C_), 256>>>(out, gnow, gnob);
}